// round 11
// baseline (speedup 1.0000x reference)
#include <cuda_runtime.h>
#include <cuda_bf16.h>
#include <cstdint>

#define N_NODES 50000
#define D_FEAT  128
#define N_EDGES 600000
#define CAP     96   // Poisson(12) in-degree: P(deg > 96) ~ 1e-60 -> never overflows

// static scratch (no cudaMalloc allowed)
__device__ int g_cnt[N_NODES];
__device__ int g_bucket[N_NODES * CAP];
__device__ int g_is64;
// self-resetting grid barrier state (zero-init; returns to zero every use)
__device__ unsigned g_arr[2];
__device__ unsigned g_dep[2];

// ---------------------------------------------------------------------------
// Software grid barrier. Requires all nblocks co-resident (grid sized from
// occupancy query). Arrive/spin/depart; the LAST departer resets both
// counters, so the barrier is clean for the next graph replay with no init.
// ---------------------------------------------------------------------------
__device__ __forceinline__ void grid_barrier(int b, unsigned nblocks) {
    __syncthreads();
    if (threadIdx.x == 0) {
        __threadfence();                       // release prior writes
        atomicAdd(&g_arr[b], 1u);
        while (*(volatile unsigned*)&g_arr[b] < nblocks) { }
        unsigned d = atomicAdd(&g_dep[b], 1u) + 1u;
        if (d == nblocks) {                    // everyone passed the spin
            g_dep[b] = 0u;
            __threadfence();
            g_arr[b] = 0u;
        }
        __threadfence();                       // acquire
    }
    __syncthreads();
}

// ---------------------------------------------------------------------------
// Fused kernel: phase0 (zero counters + dtype detect) | fill | agg.
// ---------------------------------------------------------------------------
__global__ void __launch_bounds__(256)
fused_kernel(const float* __restrict__ emb,
             float* __restrict__ out,
             const void* __restrict__ src_raw,
             const void* __restrict__ dst_raw,
             unsigned nblocks) {
    int gt = blockIdx.x * 256 + threadIdx.x;
    int gstride = (int)nblocks * 256;

    // ---- phase 0: zero counters (50000 = 12500 int4, exact) + detect ----
    for (int i = gt; i < N_NODES / 4; i += gstride)
        ((int4*)g_cnt)[i] = make_int4(0, 0, 0, 0);
    if (blockIdx.x == 0 && threadIdx.x < 32) {
        const int* p = (const int*)dst_raw;
        int lo = p[2 * threadIdx.x];
        int hi = p[2 * threadIdx.x + 1];
        bool ok = (hi == 0) && (lo >= 0) && (lo < N_NODES);
        unsigned mm = __ballot_sync(0xffffffffu, ok);
        if (threadIdx.x == 0) g_is64 = (mm == 0xffffffffu) ? 1 : 0;
    }
    grid_barrier(0, nblocks);

    // ---- phase 1: bin edges by destination ----
    if (g_is64) {
        for (int e = gt; e < N_EDGES; e += gstride) {
            long long s = __ldg((const long long*)src_raw + e);
            long long d = __ldg((const long long*)dst_raw + e);
            if (s < 0 || s >= N_NODES || d < 0 || d >= N_NODES) continue;
            int pos = atomicAdd(&g_cnt[(int)d], 1);
            if (pos < CAP) g_bucket[(int)d * CAP + pos] = (int)s;
        }
    } else {
        for (int e = gt; e < N_EDGES; e += gstride) {
            int s = __ldg((const int*)src_raw + e);
            int d = __ldg((const int*)dst_raw + e);
            if (s < 0 || s >= N_NODES || d < 0 || d >= N_NODES) continue;
            int pos = atomicAdd(&g_cnt[d], 1);
            if (pos < CAP) g_bucket[d * CAP + pos] = s;
        }
    }
    grid_barrier(1, nblocks);

    // ---- phase 2: one warp per node, grid-stride. Proven gather loop. ----
    int warp_g = gt >> 5;
    int lane = threadIdx.x & 31;
    int nwarps = gstride >> 5;
    for (int node = warp_g; node < N_NODES; node += nwarps) {
        int c = g_cnt[node];
        int m = (c < CAP) ? c : CAP;
        const int* bk = g_bucket + node * CAP;

        float4 acc = make_float4(0.f, 0.f, 0.f, 0.f);
        for (int base = 0; base < m; base += 32) {
            int lim = m - base; if (lim > 32) lim = 32;
            int s_l = (lane < lim) ? bk[base + lane] : 0;
            #pragma unroll 4
            for (int e = 0; e < lim; e++) {
                int s = __shfl_sync(0xffffffffu, s_l, e);
                float4 v = __ldg((const float4*)(emb + (long long)s * D_FEAT) + lane);
                acc.x += v.x; acc.y += v.y; acc.z += v.z; acc.w += v.w;
            }
        }
        float inv = (c > 0) ? (1.0f / (float)c) : 0.0f;
        acc.x *= inv; acc.y *= inv; acc.z *= inv; acc.w *= inv;
        ((float4*)out)[node * (D_FEAT / 4) + lane] = acc;
    }
}

// ---------------------------------------------------------------------------
// Fallback (proven R10 3-kernel path) in case occupancy query fails.
// ---------------------------------------------------------------------------
__global__ void init_kernel(const int* __restrict__ idx_as_i32) {
    int i = blockIdx.x * blockDim.x + threadIdx.x;
    if (i < N_NODES / 4) ((int4*)g_cnt)[i] = make_int4(0, 0, 0, 0);
    if (blockIdx.x == 0 && threadIdx.x < 32) {
        int lo = idx_as_i32[2 * threadIdx.x];
        int hi = idx_as_i32[2 * threadIdx.x + 1];
        bool ok = (hi == 0) && (lo >= 0) && (lo < N_NODES);
        unsigned m = __ballot_sync(0xffffffffu, ok);
        if (threadIdx.x == 0) g_is64 = (m == 0xffffffffu) ? 1 : 0;
    }
}

__global__ void fill_kernel(const void* __restrict__ src_raw,
                            const void* __restrict__ dst_raw) {
    int e = blockIdx.x * blockDim.x + threadIdx.x;
    if (e >= N_EDGES) return;
    long long s, d;
    if (g_is64) {
        s = __ldg((const long long*)src_raw + e);
        d = __ldg((const long long*)dst_raw + e);
    } else {
        s = __ldg((const int*)src_raw + e);
        d = __ldg((const int*)dst_raw + e);
    }
    if (s < 0 || s >= N_NODES || d < 0 || d >= N_NODES) return;
    int pos = atomicAdd(&g_cnt[(int)d], 1);
    if (pos < CAP) g_bucket[(int)d * CAP + pos] = (int)s;
}

__global__ void agg_kernel(const float* __restrict__ emb,
                           float* __restrict__ out) {
    int gtid = blockIdx.x * blockDim.x + threadIdx.x;
    int node = gtid >> 5;
    int lane = gtid & 31;
    if (node >= N_NODES) return;
    int c = g_cnt[node];
    int m = (c < CAP) ? c : CAP;
    const int* bk = g_bucket + node * CAP;
    float4 acc = make_float4(0.f, 0.f, 0.f, 0.f);
    for (int base = 0; base < m; base += 32) {
        int lim = m - base; if (lim > 32) lim = 32;
        int s_l = (lane < lim) ? bk[base + lane] : 0;
        #pragma unroll 4
        for (int e = 0; e < lim; e++) {
            int s = __shfl_sync(0xffffffffu, s_l, e);
            float4 v = __ldg((const float4*)(emb + (long long)s * D_FEAT) + lane);
            acc.x += v.x; acc.y += v.y; acc.z += v.z; acc.w += v.w;
        }
    }
    float inv = (c > 0) ? (1.0f / (float)c) : 0.0f;
    acc.x *= inv; acc.y *= inv; acc.z *= inv; acc.w *= inv;
    ((float4*)out)[node * (D_FEAT / 4) + lane] = acc;
}

// ---------------------------------------------------------------------------
extern "C" void kernel_launch(void* const* d_in, const int* in_sizes, int n_in,
                              void* d_out, int out_size) {
    const float* emb = (const float*)d_in[0];
    const void*  src = d_in[1];
    const void*  dst = d_in[2];
    float* out = (float*)d_out;

    int dev = 0, sms = 0, maxb = 0;
    cudaGetDevice(&dev);
    cudaDeviceGetAttribute(&sms, cudaDevAttrMultiProcessorCount, dev);
    cudaOccupancyMaxActiveBlocksPerMultiprocessor(&maxb, fused_kernel, 256, 0);

    if (sms > 0 && maxb > 0) {
        unsigned nblocks = (unsigned)(sms * maxb);   // exactly co-resident
        fused_kernel<<<nblocks, 256>>>(emb, out, src, dst, nblocks);
    } else {
        // proven 3-kernel fallback
        init_kernel<<<(N_NODES / 4 + 255) / 256, 256>>>((const int*)dst);
        fill_kernel<<<(N_EDGES + 255) / 256, 256>>>(src, dst);
        long long total_threads = (long long)N_NODES * 32;
        agg_kernel<<<(int)((total_threads + 255) / 256), 256>>>(emb, out);
    }
}

// round 12
// speedup vs baseline: 1.0470x; 1.0470x over previous
#include <cuda_runtime.h>
#include <cuda_bf16.h>
#include <cstdint>

#define N_NODES 50000
#define D_FEAT  128
#define N_EDGES 600000
#define CAP     96   // Poisson(12) in-degree: P(deg > 96) ~ 1e-60 -> never overflows

// static scratch (no cudaMalloc allowed)
__device__ int g_cnt[N_NODES];
__device__ int g_bucket[N_NODES * CAP];
__device__ int g_is64;
// self-resetting grid barrier state (zero-init; returns to zero after use)
__device__ unsigned g_arr;
__device__ unsigned g_dep;

// ---------------------------------------------------------------------------
// Software grid barrier (validated in R11). Requires all nblocks co-resident.
// Last departer resets both counters -> clean for every graph replay.
// ---------------------------------------------------------------------------
__device__ __forceinline__ void grid_barrier(unsigned nblocks) {
    __syncthreads();
    if (threadIdx.x == 0) {
        __threadfence();                        // release phase-0 writes
        atomicAdd(&g_arr, 1u);
        while (*(volatile unsigned*)&g_arr < nblocks) { }
        unsigned d = atomicAdd(&g_dep, 1u) + 1u;
        if (d == nblocks) {                     // everyone passed the spin
            g_dep = 0u;
            __threadfence();
            g_arr = 0u;
        }
        __threadfence();                        // acquire
    }
    __syncthreads();
}

// ---------------------------------------------------------------------------
// Fused front kernel: phase 0 zero counters + dtype detect | barrier | fill.
// (agg deliberately NOT fused: R11 showed the gather loop degrades 27->42us
//  when index pointers / grid-stride state are live in the same kernel.)
// ---------------------------------------------------------------------------
__global__ void __launch_bounds__(256)
init_fill_kernel(const void* __restrict__ src_raw,
                 const void* __restrict__ dst_raw,
                 unsigned nblocks) {
    int gt = blockIdx.x * 256 + threadIdx.x;
    int gstride = (int)nblocks * 256;

    // phase 0: zero counters (50000 = 12500 int4, exact) + detect dtype.
    for (int i = gt; i < N_NODES / 4; i += gstride)
        ((int4*)g_cnt)[i] = make_int4(0, 0, 0, 0);
    if (blockIdx.x == 0 && threadIdx.x < 32) {
        const int* p = (const int*)dst_raw;
        int lo = p[2 * threadIdx.x];
        int hi = p[2 * threadIdx.x + 1];
        bool ok = (hi == 0) && (lo >= 0) && (lo < N_NODES);
        unsigned mm = __ballot_sync(0xffffffffu, ok);
        if (threadIdx.x == 0) g_is64 = (mm == 0xffffffffu) ? 1 : 0;
    }

    grid_barrier(nblocks);

    // phase 1: bin edges by destination (grid-stride).
    if (g_is64) {
        for (int e = gt; e < N_EDGES; e += gstride) {
            long long s = __ldg((const long long*)src_raw + e);
            long long d = __ldg((const long long*)dst_raw + e);
            if (s < 0 || s >= N_NODES || d < 0 || d >= N_NODES) continue;
            int pos = atomicAdd(&g_cnt[(int)d], 1);
            if (pos < CAP) g_bucket[(int)d * CAP + pos] = (int)s;
        }
    } else {
        for (int e = gt; e < N_EDGES; e += gstride) {
            int s = __ldg((const int*)src_raw + e);
            int d = __ldg((const int*)dst_raw + e);
            if (s < 0 || s >= N_NODES || d < 0 || d >= N_NODES) continue;
            int pos = atomicAdd(&g_cnt[d], 1);
            if (pos < CAP) g_bucket[d * CAP + pos] = s;
        }
    }
}

// ---------------------------------------------------------------------------
// agg: PRISTINE 26.7us form. One warp per node; gather-reduce L2-resident
// rows; write mean once. Leaf, (emb,out) args only, no resets, no barriers
// (R6-R11: any perturbation serializes the load batching).
// ---------------------------------------------------------------------------
__global__ void agg_kernel(const float* __restrict__ emb,
                           float* __restrict__ out) {
    int gtid = blockIdx.x * blockDim.x + threadIdx.x;
    int node = gtid >> 5;
    int lane = gtid & 31;
    if (node >= N_NODES) return;

    int c = g_cnt[node];
    int m = (c < CAP) ? c : CAP;
    const int* bk = g_bucket + node * CAP;

    float4 acc = make_float4(0.f, 0.f, 0.f, 0.f);

    for (int base = 0; base < m; base += 32) {
        int lim = m - base; if (lim > 32) lim = 32;
        int s_l = (lane < lim) ? bk[base + lane] : 0;
        #pragma unroll 4
        for (int e = 0; e < lim; e++) {
            int s = __shfl_sync(0xffffffffu, s_l, e);
            float4 v = __ldg((const float4*)(emb + (long long)s * D_FEAT) + lane);
            acc.x += v.x; acc.y += v.y; acc.z += v.z; acc.w += v.w;
        }
    }

    float inv = (c > 0) ? (1.0f / (float)c) : 0.0f;
    acc.x *= inv; acc.y *= inv; acc.z *= inv; acc.w *= inv;
    ((float4*)out)[node * (D_FEAT / 4) + lane] = acc;
}

// ---------------------------------------------------------------------------
// Fallback pieces (proven R10 path) if occupancy query fails.
// ---------------------------------------------------------------------------
__global__ void init_kernel(const int* __restrict__ idx_as_i32) {
    int i = blockIdx.x * blockDim.x + threadIdx.x;
    if (i < N_NODES / 4) ((int4*)g_cnt)[i] = make_int4(0, 0, 0, 0);
    if (blockIdx.x == 0 && threadIdx.x < 32) {
        int lo = idx_as_i32[2 * threadIdx.x];
        int hi = idx_as_i32[2 * threadIdx.x + 1];
        bool ok = (hi == 0) && (lo >= 0) && (lo < N_NODES);
        unsigned m = __ballot_sync(0xffffffffu, ok);
        if (threadIdx.x == 0) g_is64 = (m == 0xffffffffu) ? 1 : 0;
    }
}

__global__ void fill_kernel(const void* __restrict__ src_raw,
                            const void* __restrict__ dst_raw) {
    int e = blockIdx.x * blockDim.x + threadIdx.x;
    if (e >= N_EDGES) return;
    long long s, d;
    if (g_is64) {
        s = __ldg((const long long*)src_raw + e);
        d = __ldg((const long long*)dst_raw + e);
    } else {
        s = __ldg((const int*)src_raw + e);
        d = __ldg((const int*)dst_raw + e);
    }
    if (s < 0 || s >= N_NODES || d < 0 || d >= N_NODES) return;
    int pos = atomicAdd(&g_cnt[(int)d], 1);
    if (pos < CAP) g_bucket[(int)d * CAP + pos] = (int)s;
}

// ---------------------------------------------------------------------------
extern "C" void kernel_launch(void* const* d_in, const int* in_sizes, int n_in,
                              void* d_out, int out_size) {
    const float* emb = (const float*)d_in[0];
    const void*  src = d_in[1];
    const void*  dst = d_in[2];
    float* out = (float*)d_out;

    int dev = 0, sms = 0, maxb = 0;
    cudaGetDevice(&dev);
    cudaDeviceGetAttribute(&sms, cudaDevAttrMultiProcessorCount, dev);
    cudaOccupancyMaxActiveBlocksPerMultiprocessor(&maxb, init_fill_kernel, 256, 0);

    if (sms > 0 && maxb > 0) {
        unsigned nblocks = (unsigned)(sms * maxb);   // exactly co-resident
        init_fill_kernel<<<nblocks, 256>>>(src, dst, nblocks);
    } else {
        init_kernel<<<(N_NODES / 4 + 255) / 256, 256>>>((const int*)dst);
        fill_kernel<<<(N_EDGES + 255) / 256, 256>>>(src, dst);
    }

    long long total_threads = (long long)N_NODES * 32;
    agg_kernel<<<(int)((total_threads + 255) / 256), 256>>>(emb, out);
}

// round 13
// speedup vs baseline: 1.1644x; 1.1122x over previous
#include <cuda_runtime.h>
#include <cuda_fp16.h>
#include <cstdint>

#define N_NODES 50000
#define D_FEAT  128
#define N_EDGES 600000
#define CAP     96   // Poisson(12) in-degree: P(deg > 96) ~ 1e-60 -> never overflows

// static scratch (no cudaMalloc allowed)
__device__ int    g_cnt[N_NODES];
__device__ int    g_bucket[N_NODES * CAP];
__device__ int    g_is64;
__device__ __half g_embh[N_NODES * D_FEAT];   // fp16 copy of the table (12.8 MB)

// ---------------------------------------------------------------------------
// Kernel 1: convert table f32 -> f16 (one thread per 4 elements), zero the
// counters, and detect index dtype (warp ballot in block 0). Streaming kernel,
// scheduling not fragile -> safe to fold phase 0 in.
// ---------------------------------------------------------------------------
__global__ void __launch_bounds__(256)
conv_init_kernel(const float* __restrict__ emb,
                 const int* __restrict__ idx_as_i32) {
    int i = blockIdx.x * 256 + threadIdx.x;

    if (i < N_NODES * D_FEAT / 4) {
        float4 v = __ldg((const float4*)emb + i);
        __half2 a = __floats2half2_rn(v.x, v.y);
        __half2 b = __floats2half2_rn(v.z, v.w);
        uint2 r;
        r.x = *reinterpret_cast<unsigned*>(&a);
        r.y = *reinterpret_cast<unsigned*>(&b);
        ((uint2*)g_embh)[i] = r;
    }
    if (i < N_NODES / 4) {
        ((int4*)g_cnt)[i] = make_int4(0, 0, 0, 0);
    }
    if (blockIdx.x == 0 && threadIdx.x < 32) {
        int lo = idx_as_i32[2 * threadIdx.x];
        int hi = idx_as_i32[2 * threadIdx.x + 1];
        bool ok = (hi == 0) && (lo >= 0) && (lo < N_NODES);
        unsigned m = __ballot_sync(0xffffffffu, ok);
        if (threadIdx.x == 0) g_is64 = (m == 0xffffffffu) ? 1 : 0;
    }
}

// ---------------------------------------------------------------------------
// Kernel 2: bin edges by destination. One thread per edge (proven R10 form).
// ---------------------------------------------------------------------------
__global__ void fill_kernel(const void* __restrict__ src_raw,
                            const void* __restrict__ dst_raw) {
    int e = blockIdx.x * blockDim.x + threadIdx.x;
    if (e >= N_EDGES) return;

    long long s, d;
    if (g_is64) {
        s = __ldg((const long long*)src_raw + e);
        d = __ldg((const long long*)dst_raw + e);
    } else {
        s = __ldg((const int*)src_raw + e);
        d = __ldg((const int*)dst_raw + e);
    }
    if (s < 0 || s >= N_NODES || d < 0 || d >= N_NODES) return;

    int pos = atomicAdd(&g_cnt[(int)d], 1);
    if (pos < CAP) g_bucket[(int)d * CAP + pos] = (int)s;
}

// ---------------------------------------------------------------------------
// Kernel 3: one warp per node, gather-reduce in fp16 (halved L2 bytes),
// accumulate f32, write mean once. Structure identical to the pristine
// 27.1us loop (leaf kernel, minimal args, loads front-batchable); each lane
// loads 4 halves (uint2) and owns output columns lane*4 .. lane*4+3.
// ---------------------------------------------------------------------------
__global__ void agg_kernel(float* __restrict__ out) {
    int gtid = blockIdx.x * blockDim.x + threadIdx.x;
    int node = gtid >> 5;
    int lane = gtid & 31;
    if (node >= N_NODES) return;

    int c = g_cnt[node];
    int m = (c < CAP) ? c : CAP;
    const int* bk = g_bucket + node * CAP;

    float4 acc = make_float4(0.f, 0.f, 0.f, 0.f);

    for (int base = 0; base < m; base += 32) {
        int lim = m - base; if (lim > 32) lim = 32;
        int s_l = (lane < lim) ? bk[base + lane] : 0;
        #pragma unroll 4
        for (int e = 0; e < lim; e++) {
            int s = __shfl_sync(0xffffffffu, s_l, e);
            uint2 raw = __ldg((const uint2*)(g_embh + (long long)s * D_FEAT) + lane);
            __half2 h01 = *reinterpret_cast<__half2*>(&raw.x);
            __half2 h23 = *reinterpret_cast<__half2*>(&raw.y);
            float2 f01 = __half22float2(h01);
            float2 f23 = __half22float2(h23);
            acc.x += f01.x; acc.y += f01.y; acc.z += f23.x; acc.w += f23.y;
        }
    }

    float inv = (c > 0) ? (1.0f / (float)c) : 0.0f;
    acc.x *= inv; acc.y *= inv; acc.z *= inv; acc.w *= inv;
    ((float4*)out)[node * (D_FEAT / 4) + lane] = acc;
}

// ---------------------------------------------------------------------------
extern "C" void kernel_launch(void* const* d_in, const int* in_sizes, int n_in,
                              void* d_out, int out_size) {
    const float* emb = (const float*)d_in[0];
    const void*  src = d_in[1];
    const void*  dst = d_in[2];
    float* out = (float*)d_out;

    {
        int total = N_NODES * D_FEAT / 4;    // 1.6M threads
        conv_init_kernel<<<(total + 255) / 256, 256>>>(emb, (const int*)dst);
    }
    fill_kernel<<<(N_EDGES + 255) / 256, 256>>>(src, dst);
    {
        long long total_threads = (long long)N_NODES * 32;
        agg_kernel<<<(int)((total_threads + 255) / 256), 256>>>(out);
    }
}